// round 13
// baseline (speedup 1.0000x reference)
#include <cuda_runtime.h>
#include <math_constants.h>

// BarycentricPooling — closed form (R1 derivation):
// The reference's final sinkhorn half-step computes
//   g[n,k] = -EPS * logsumexp_s(log_a + (f[n,s]-C[n,s,k])/EPS)
// and then reads the transport plan's second marginal
//   hist[n,k] = exp(g/EPS + log_b + logsumexp_s(log_a + (f-C)/EPS))
//             = exp(log_b[k])          (the lse term is -g/EPS by definition)
// so hist[n,:] == softmax(log_prior) exactly for every n; the segment mean of
// identical rows is that row, and the empty-graph fallback is the same value.
// Output [B=256, K=64] = softmax(log_codebook_prior) broadcast over rows.
//
// FINAL champion (identical binary benched 4x: ncu 3.94/3.97/3.97/4.22us,
// wall 4.61/4.51/6.91/4.61 — all deltas are sampling noise around the
// sm_103a launch/dispatch/drain floor). Launch-shape curve (ncu):
//   4x1024: 4.35 | 8x512: 3.94 | 16x256: 4.03 | 32x128: 4.32
// -> minimum at 8 CTAs x 512 threads.
// Per thread: 1 LDG.128 of its own output chunk, 1 broadcast SHFL (common
// softmax shift — exact by shift-invariance), 4 MUFU exp, 4-step butterfly
// over 16-lane groups (each chunk appears twice per warp, so the group sum
// is the exact 64-way total), RCP, 1 STG.128. ~450 cycles of work total.

__global__ void __launch_bounds__(512, 1)
prior_broadcast_kernel(const float4* __restrict__ lp4,
                       float4* __restrict__ out4) {
    const int i = blockIdx.x * blockDim.x + threadIdx.x;
    const int j = i & 15;                 // chunk index, ready before the load

    float4 v = lp4[j];                    // one LDG.128 (L1/L2 broadcast)

    // Warp-uniform shift: lane 0's local max (any common constant is exact).
    float lm = fmaxf(fmaxf(v.x, v.y), fmaxf(v.z, v.w));
    float shift = __shfl_sync(0xffffffff, lm, 0);

    float e0 = __expf(v.x - shift);
    float e1 = __expf(v.y - shift);
    float e2 = __expf(v.z - shift);
    float e3 = __expf(v.w - shift);
    float s = (e0 + e1) + (e2 + e3);

    // Lanes j and j+16 hold identical chunks: reduce within 16-lane groups.
    #pragma unroll
    for (int o = 8; o > 0; o >>= 1)
        s += __shfl_xor_sync(0xffffffff, s, o);

    float inv = __frcp_rn(s);
    out4[i] = make_float4(e0 * inv, e1 * inv, e2 * inv, e3 * inv);
}

// Generic fallback (any K / size) — never taken for this problem shape.
__global__ void prior_broadcast_generic(const float* __restrict__ log_prior,
                                        float* __restrict__ out,
                                        int K, int total) {
    extern __shared__ float soft[];
    const int tid = threadIdx.x;
    if (tid < K) {
        float m = -CUDART_INF_F;
        for (int j = 0; j < K; ++j) m = fmaxf(m, log_prior[j]);
        float s = 0.0f;
        for (int j = 0; j < K; ++j) s += __expf(log_prior[j] - m);
        soft[tid] = __expf(log_prior[tid] - m) / s;
    }
    __syncthreads();
    for (int i = blockIdx.x * blockDim.x + tid; i < total;
         i += gridDim.x * blockDim.x)
        out[i] = soft[i % K];
}

extern "C" void kernel_launch(void* const* d_in, const int* in_sizes, int n_in,
                              void* d_out, int out_size) {
    // metadata order: node_distributions, batch_idx, codebook, log_codebook_prior
    const float* log_prior = (const float*)d_in[3];
    const int K = in_sizes[3];  // 64

    const int threads = 512;
    if (K == 64 && (out_size & (4 * threads - 1)) == 0) {
        int total4 = out_size >> 2;          // 4096
        int blocks = total4 / threads;       // 8 — exact cover, no tail
        prior_broadcast_kernel<<<blocks, threads>>>(
            (const float4*)log_prior, (float4*)d_out);
    } else {
        const int t2 = 256;
        int blocks = (out_size + t2 - 1) / t2;
        if (blocks > 64) blocks = 64;
        if (blocks < 1) blocks = 1;
        prior_broadcast_generic<<<blocks, t2, (size_t)K * sizeof(float)>>>(
            log_prior, (float*)d_out, K, out_size);
    }
}

// round 14
// speedup vs baseline: 1.0386x; 1.0386x over previous
#include <cuda_runtime.h>
#include <math_constants.h>

// BarycentricPooling — closed form (R1 derivation):
// The reference's final sinkhorn half-step computes
//   g[n,k] = -EPS * logsumexp_s(log_a + (f[n,s]-C[n,s,k])/EPS)
// and then reads the transport plan's second marginal
//   hist[n,k] = exp(g/EPS + log_b + logsumexp_s(log_a + (f-C)/EPS))
//             = exp(log_b[k])          (the lse term is -g/EPS by definition)
// so hist[n,:] == softmax(log_prior) exactly for every n; the segment mean of
// identical rows is that row, and the empty-graph fallback is the same value.
// Output [B=256, K=64] = softmax(log_codebook_prior) broadcast over rows.
//
// FINAL champion (identical binary benched 5x: ncu 3.94/3.97/3.97/4.22/4.10,
// wall 4.61/4.51/6.91/4.61/6.88 — wall is bimodal harness noise, uncorrelated
// with kernel time). Launch-shape curve (ncu):
//   4x1024: 4.35 | 8x512: 3.94 | 16x256: 4.03 | 32x128: 4.32
// -> minimum at 8 CTAs x 512 threads.
// Per thread: 1 LDG.128 of its own output chunk, 1 broadcast SHFL (common
// softmax shift — exact by shift-invariance), 4 MUFU exp, 4-step butterfly
// over 16-lane groups (each chunk appears twice per warp, so the group sum
// is the exact 64-way total), RCP, 1 STG.128. ~450 cycles of work total;
// the remainder is the sm_103a launch/dispatch/drain floor.

__global__ void __launch_bounds__(512, 1)
prior_broadcast_kernel(const float4* __restrict__ lp4,
                       float4* __restrict__ out4) {
    const int i = blockIdx.x * blockDim.x + threadIdx.x;
    const int j = i & 15;                 // chunk index, ready before the load

    float4 v = lp4[j];                    // one LDG.128 (L1/L2 broadcast)

    // Warp-uniform shift: lane 0's local max (any common constant is exact).
    float lm = fmaxf(fmaxf(v.x, v.y), fmaxf(v.z, v.w));
    float shift = __shfl_sync(0xffffffff, lm, 0);

    float e0 = __expf(v.x - shift);
    float e1 = __expf(v.y - shift);
    float e2 = __expf(v.z - shift);
    float e3 = __expf(v.w - shift);
    float s = (e0 + e1) + (e2 + e3);

    // Lanes j and j+16 hold identical chunks: reduce within 16-lane groups.
    #pragma unroll
    for (int o = 8; o > 0; o >>= 1)
        s += __shfl_xor_sync(0xffffffff, s, o);

    float inv = __frcp_rn(s);
    out4[i] = make_float4(e0 * inv, e1 * inv, e2 * inv, e3 * inv);
}

// Generic fallback (any K / size) — never taken for this problem shape.
__global__ void prior_broadcast_generic(const float* __restrict__ log_prior,
                                        float* __restrict__ out,
                                        int K, int total) {
    extern __shared__ float soft[];
    const int tid = threadIdx.x;
    if (tid < K) {
        float m = -CUDART_INF_F;
        for (int j = 0; j < K; ++j) m = fmaxf(m, log_prior[j]);
        float s = 0.0f;
        for (int j = 0; j < K; ++j) s += __expf(log_prior[j] - m);
        soft[tid] = __expf(log_prior[tid] - m) / s;
    }
    __syncthreads();
    for (int i = blockIdx.x * blockDim.x + tid; i < total;
         i += gridDim.x * blockDim.x)
        out[i] = soft[i % K];
}

extern "C" void kernel_launch(void* const* d_in, const int* in_sizes, int n_in,
                              void* d_out, int out_size) {
    // metadata order: node_distributions, batch_idx, codebook, log_codebook_prior
    const float* log_prior = (const float*)d_in[3];
    const int K = in_sizes[3];  // 64

    const int threads = 512;
    if (K == 64 && (out_size & (4 * threads - 1)) == 0) {
        int total4 = out_size >> 2;          // 4096
        int blocks = total4 / threads;       // 8 — exact cover, no tail
        prior_broadcast_kernel<<<blocks, threads>>>(
            (const float4*)log_prior, (float4*)d_out);
    } else {
        const int t2 = 256;
        int blocks = (out_size + t2 - 1) / t2;
        if (blocks > 64) blocks = 64;
        if (blocks < 1) blocks = 1;
        prior_broadcast_generic<<<blocks, t2, (size_t)K * sizeof(float)>>>(
            log_prior, (float*)d_out, K, out_size);
    }
}

// round 15
// speedup vs baseline: 1.5035x; 1.4476x over previous
#include <cuda_runtime.h>
#include <math_constants.h>

// BarycentricPooling — closed form (R1 derivation):
// The reference's final sinkhorn half-step computes
//   g[n,k] = -EPS * logsumexp_s(log_a + (f[n,s]-C[n,s,k])/EPS)
// and then reads the transport plan's second marginal
//   hist[n,k] = exp(g/EPS + log_b + logsumexp_s(log_a + (f-C)/EPS))
//             = exp(log_b[k])          (the lse term is -g/EPS by definition)
// so hist[n,:] == softmax(log_prior) exactly for every n; the segment mean of
// identical rows is that row, and the empty-graph fallback is the same value.
// Output [B=256, K=64] = softmax(log_codebook_prior) broadcast over rows.
//
// FINAL champion (identical binary benched 6x:
//   ncu  3.94/3.97/3.97/4.22/4.10/4.13 us
//   wall 4.61/4.51/6.91/4.61/6.88/6.62 us — bimodal harness noise,
//   uncorrelated with kernel time).
// Launch-shape curve (ncu): 4x1024: 4.35 | 8x512: 3.94 | 16x256: 4.03 |
// 32x128: 4.32 -> minimum at 8 CTAs x 512 threads.
// Per thread: 1 LDG.128 of its own output chunk, 1 broadcast SHFL (common
// softmax shift — exact by shift-invariance), 4 MUFU exp, 4-step butterfly
// over 16-lane groups (each chunk appears twice per warp, so the group sum
// is the exact 64-way total), RCP, 1 STG.128. ~450 cycles of work total;
// the remainder is the sm_103a launch/dispatch/drain floor.

__global__ void __launch_bounds__(512, 1)
prior_broadcast_kernel(const float4* __restrict__ lp4,
                       float4* __restrict__ out4) {
    const int i = blockIdx.x * blockDim.x + threadIdx.x;
    const int j = i & 15;                 // chunk index, ready before the load

    float4 v = lp4[j];                    // one LDG.128 (L1/L2 broadcast)

    // Warp-uniform shift: lane 0's local max (any common constant is exact).
    float lm = fmaxf(fmaxf(v.x, v.y), fmaxf(v.z, v.w));
    float shift = __shfl_sync(0xffffffff, lm, 0);

    float e0 = __expf(v.x - shift);
    float e1 = __expf(v.y - shift);
    float e2 = __expf(v.z - shift);
    float e3 = __expf(v.w - shift);
    float s = (e0 + e1) + (e2 + e3);

    // Lanes j and j+16 hold identical chunks: reduce within 16-lane groups.
    #pragma unroll
    for (int o = 8; o > 0; o >>= 1)
        s += __shfl_xor_sync(0xffffffff, s, o);

    float inv = __frcp_rn(s);
    out4[i] = make_float4(e0 * inv, e1 * inv, e2 * inv, e3 * inv);
}

// Generic fallback (any K / size) — never taken for this problem shape.
__global__ void prior_broadcast_generic(const float* __restrict__ log_prior,
                                        float* __restrict__ out,
                                        int K, int total) {
    extern __shared__ float soft[];
    const int tid = threadIdx.x;
    if (tid < K) {
        float m = -CUDART_INF_F;
        for (int j = 0; j < K; ++j) m = fmaxf(m, log_prior[j]);
        float s = 0.0f;
        for (int j = 0; j < K; ++j) s += __expf(log_prior[j] - m);
        soft[tid] = __expf(log_prior[tid] - m) / s;
    }
    __syncthreads();
    for (int i = blockIdx.x * blockDim.x + tid; i < total;
         i += gridDim.x * blockDim.x)
        out[i] = soft[i % K];
}

extern "C" void kernel_launch(void* const* d_in, const int* in_sizes, int n_in,
                              void* d_out, int out_size) {
    // metadata order: node_distributions, batch_idx, codebook, log_codebook_prior
    const float* log_prior = (const float*)d_in[3];
    const int K = in_sizes[3];  // 64

    const int threads = 512;
    if (K == 64 && (out_size & (4 * threads - 1)) == 0) {
        int total4 = out_size >> 2;          // 4096
        int blocks = total4 / threads;       // 8 — exact cover, no tail
        prior_broadcast_kernel<<<blocks, threads>>>(
            (const float4*)log_prior, (float4*)d_out);
    } else {
        const int t2 = 256;
        int blocks = (out_size + t2 - 1) / t2;
        if (blocks > 64) blocks = 64;
        if (blocks < 1) blocks = 1;
        prior_broadcast_generic<<<blocks, t2, (size_t)K * sizeof(float)>>>(
            log_prior, (float*)d_out, K, out_size);
    }
}